// round 3
// baseline (speedup 1.0000x reference)
#include <cuda_runtime.h>
#include <cuda_bf16.h>
#include <cstdint>

// Problem constants
#define GH 8
#define GW 8
#define RR 64          // regions
#define BB 8           // batch
#define CIN 128
#define COUT 256
#define TH 32          // tile h
#define TW 32          // tile w
#define NPIX 1024      // TH*TW
#define NN 8192        // BB*NPIX  (GEMM N per region)
#define KK 256         // CIN*2    (GEMM K per region: [gelu(y); x])
#define EPSV 1e-5f

// ---------------- scratch (device globals; no runtime allocation) -------------
// S: per-region stacked operand, layout [r][k][n], k in [0,256): k<128 -> gelu path, k>=128 -> raw x
__device__ float g_S[(size_t)RR * KK * NN];          // 512 MB
// Folded weight: [r][o][k], k<128 -> sc2*pw_w, k>=128 -> res_w
__device__ float g_W[(size_t)RR * COUT * KK];        // 16 MB
__device__ float g_bias[RR * COUT];                  // sh2

// ---------------- kernel 0: fold BN2 into weights -----------------------------
__global__ __launch_bounds__(256) void k_prep(const float* __restrict__ pw_w,
                                              const float* __restrict__ res_w,
                                              const float* __restrict__ g2,
                                              const float* __restrict__ b2,
                                              const float* __restrict__ m2,
                                              const float* __restrict__ v2) {
    int idx = blockIdx.x * 256 + threadIdx.x;           // over RR*COUT*KK = 4.19M
    int r = idx >> 16;                                  // /65536
    int rem = idx & 65535;
    int o = rem >> 8;
    int k = rem & 255;
    int ro = r * COUT + o;
    float rs = rsqrtf(v2[ro] + EPSV);
    float sc = g2[ro] * rs;
    float wv;
    if (k < CIN) wv = sc * pw_w[(size_t)ro * CIN + k];
    else         wv = res_w[(size_t)ro * CIN + (k - CIN)];
    g_W[idx] = wv;
    if (k == 0) g_bias[ro] = b2[ro] - g2[ro] * m2[ro] * rs;
}

// ---------------- kernel 1: depthwise 3x3 + BN1 + exact GELU, build S ---------
__global__ __launch_bounds__(256) void k_dw(const float* __restrict__ x,
                                            const float* __restrict__ dw_w,
                                            const float* __restrict__ g1,
                                            const float* __restrict__ b1,
                                            const float* __restrict__ m1,
                                            const float* __restrict__ v1) {
    __shared__ float t[TH][TW];
    int bid = blockIdx.x;                 // RR*BB*CIN = 65536 blocks
    int c  = bid & 127;
    int bb = (bid >> 7) & 7;
    int r  = bid >> 10;
    int gh = r >> 3, gw = r & 7;
    int tid = threadIdx.x;

    const float* xp = x + (((size_t)(bb * CIN + c) * 256 + gh * TH) * 256 + gw * TW);
    #pragma unroll
    for (int p = tid; p < NPIX; p += 256) {
        int row = p >> 5, col = p & 31;
        t[row][col] = xp[(size_t)row * 256 + col];
    }

    float w[9];
    const float* wp = dw_w + (size_t)(r * CIN + c) * 9;
    #pragma unroll
    for (int i = 0; i < 9; i++) w[i] = wp[i];

    int rc = r * CIN + c;
    float rs = rsqrtf(v1[rc] + EPSV);
    float sc = g1[rc] * rs;
    float sh = b1[rc] - g1[rc] * m1[rc] * rs;

    __syncthreads();

    size_t base  = ((size_t)(r * KK + c)) * NN + (size_t)bb * NPIX;
    size_t basex = ((size_t)(r * KK + CIN + c)) * NN + (size_t)bb * NPIX;

    #pragma unroll
    for (int p = tid; p < NPIX; p += 256) {
        int row = p >> 5, col = p & 31;
        float s = 0.f;
        #pragma unroll
        for (int dr = -1; dr <= 1; dr++) {
            #pragma unroll
            for (int dc = -1; dc <= 1; dc++) {
                int rr2 = row + dr, cc2 = col + dc;
                float vv = (rr2 >= 0 && rr2 < TH && cc2 >= 0 && cc2 < TW) ? t[rr2][cc2] : 0.f;
                s = fmaf(vv, w[(dr + 1) * 3 + (dc + 1)], s);
            }
        }
        float yv = fmaf(s, sc, sh);
        float gv = yv * normcdff(yv);        // exact GELU: x * Phi(x)
        g_S[base + p]  = gv;
        g_S[basex + p] = t[row][col];
    }
}

// ---------------- kernel 2: per-region GEMM + bias + reassembly ---------------
// C[r][o][n] = sum_k W[r][o][k] * S[r][k][n] + bias[r][o]
// out[b][o][gh*32+prow][gw*32+pcol],  n = b*1024 + prow*32 + pcol
#define BM 128
#define BN 128
#define BKS 8

__global__ __launch_bounds__(256) void k_gemm(float* __restrict__ out) {
    __shared__ float As[BKS][BM + 4];
    __shared__ float Bs[BKS][BN];

    int r  = blockIdx.z;
    int m0 = blockIdx.y * BM;
    int n0 = blockIdx.x * BN;
    const float* A = g_W + (size_t)r * COUT * KK;
    const float* Bm = g_S + (size_t)r * KK * NN;

    int tid = threadIdx.x;
    int tx = tid & 15, ty = tid >> 4;

    // A-tile load mapping: row = tid>>1 (0..127), 4 consecutive k at (tid&1)*4
    int a_row = tid >> 1;
    int a_k4  = (tid & 1) * 4;
    // B-tile load mapping: krow = tid>>5 (0..7), 4 consecutive n at (tid&31)*4
    int b_kr  = tid >> 5;
    int b_n4  = (tid & 31) * 4;

    float acc[8][8];
    #pragma unroll
    for (int i = 0; i < 8; i++)
        #pragma unroll
        for (int j = 0; j < 8; j++) acc[i][j] = 0.f;

    for (int k0 = 0; k0 < KK; k0 += BKS) {
        float4 av = *(const float4*)&A[(size_t)(m0 + a_row) * KK + k0 + a_k4];
        As[a_k4 + 0][a_row] = av.x;
        As[a_k4 + 1][a_row] = av.y;
        As[a_k4 + 2][a_row] = av.z;
        As[a_k4 + 3][a_row] = av.w;
        float4 bv = *(const float4*)&Bm[(size_t)(k0 + b_kr) * NN + n0 + b_n4];
        *(float4*)&Bs[b_kr][b_n4] = bv;
        __syncthreads();

        #pragma unroll
        for (int kk = 0; kk < BKS; kk++) {
            float4 a0 = *(const float4*)&As[kk][ty * 8];
            float4 a1 = *(const float4*)&As[kk][ty * 8 + 4];
            float4 c0 = *(const float4*)&Bs[kk][tx * 8];
            float4 c1 = *(const float4*)&Bs[kk][tx * 8 + 4];
            float ar[8] = {a0.x, a0.y, a0.z, a0.w, a1.x, a1.y, a1.z, a1.w};
            float br[8] = {c0.x, c0.y, c0.z, c0.w, c1.x, c1.y, c1.z, c1.w};
            #pragma unroll
            for (int i = 0; i < 8; i++)
                #pragma unroll
                for (int j = 0; j < 8; j++)
                    acc[i][j] = fmaf(ar[i], br[j], acc[i][j]);
        }
        __syncthreads();
    }

    // epilogue: bias + scatter back into [B, COUT, 256, 256]
    int gh = r >> 3, gw = r & 7;
    int n_base = n0 + tx * 8;
    int b_idx  = n_base >> 10;
    int hw     = n_base & 1023;
    int prow   = hw >> 5, pcol = hw & 31;

    #pragma unroll
    for (int i = 0; i < 8; i++) {
        int mo = m0 + ty * 8 + i;
        float bi = g_bias[r * COUT + mo];
        size_t ooff = (((size_t)(b_idx * COUT + mo) * 256 + gh * TH + prow) * 256 + gw * TW + pcol);
        float4 v0 = make_float4(acc[i][0] + bi, acc[i][1] + bi, acc[i][2] + bi, acc[i][3] + bi);
        float4 v1 = make_float4(acc[i][4] + bi, acc[i][5] + bi, acc[i][6] + bi, acc[i][7] + bi);
        *(float4*)&out[ooff]     = v0;
        *(float4*)&out[ooff + 4] = v1;
    }
}

// ---------------- launch ------------------------------------------------------
extern "C" void kernel_launch(void* const* d_in, const int* in_sizes, int n_in,
                              void* d_out, int out_size) {
    const float* x     = (const float*)d_in[0];
    const float* dw_w  = (const float*)d_in[1];
    const float* bn1_g = (const float*)d_in[2];
    const float* bn1_b = (const float*)d_in[3];
    const float* bn1_m = (const float*)d_in[4];
    const float* bn1_v = (const float*)d_in[5];
    const float* pw_w  = (const float*)d_in[6];
    const float* bn2_g = (const float*)d_in[7];
    const float* bn2_b = (const float*)d_in[8];
    const float* bn2_m = (const float*)d_in[9];
    const float* bn2_v = (const float*)d_in[10];
    const float* res_w = (const float*)d_in[11];
    float* out = (float*)d_out;

    // fold BN2 into GEMM weights + bias
    k_prep<<<(RR * COUT * KK) / 256, 256>>>(pw_w, res_w, bn2_g, bn2_b, bn2_m, bn2_v);
    // depthwise + BN1 + GELU, build stacked operand S
    k_dw<<<RR * BB * CIN, 256>>>(x, dw_w, bn1_g, bn1_b, bn1_m, bn1_v);
    // batched per-region GEMM + bias + reassembly
    dim3 grid(NN / BN, COUT / BM, RR);
    k_gemm<<<grid, 256>>>(out);
}

// round 4
// speedup vs baseline: 1.0003x; 1.0003x over previous
#include <cuda_runtime.h>
#include <cuda_bf16.h>
#include <cstdint>

// Problem constants
#define GH 8
#define GW 8
#define RR 64          // regions
#define BB 8           // batch
#define CIN 128
#define COUT 256
#define TH 32          // tile h
#define TW 32          // tile w
#define NPIX 1024      // TH*TW
#define NN 8192        // BB*NPIX  (GEMM N per region)
#define KK 256         // CIN*2    (GEMM K per region: [gelu(y); x])
#define EPSV 1e-5f

// ---------------- scratch (device globals; no runtime allocation) -------------
// S: per-region stacked operand, layout [r][k][n], k in [0,256): k<128 -> gelu path, k>=128 -> raw x
__device__ float g_S[(size_t)RR * KK * NN];          // 512 MB
// Folded weight: [r][o][k], k<128 -> sc2*pw_w, k>=128 -> res_w
__device__ float g_W[(size_t)RR * COUT * KK];        // 16 MB
__device__ float g_bias[RR * COUT];                  // sh2

// ---------------- kernel 0: fold BN2 into weights -----------------------------
__global__ __launch_bounds__(256) void k_prep(const float* __restrict__ pw_w,
                                              const float* __restrict__ res_w,
                                              const float* __restrict__ g2,
                                              const float* __restrict__ b2,
                                              const float* __restrict__ m2,
                                              const float* __restrict__ v2) {
    int idx = blockIdx.x * 256 + threadIdx.x;           // over RR*COUT*KK = 4.19M
    int r = idx >> 16;                                  // /65536
    int rem = idx & 65535;
    int o = rem >> 8;
    int k = rem & 255;
    int ro = r * COUT + o;
    float rs = rsqrtf(v2[ro] + EPSV);
    float sc = g2[ro] * rs;
    float wv;
    if (k < CIN) wv = sc * pw_w[(size_t)ro * CIN + k];
    else         wv = res_w[(size_t)ro * CIN + (k - CIN)];
    g_W[idx] = wv;
    if (k == 0) g_bias[ro] = b2[ro] - g2[ro] * m2[ro] * rs;
}

// ---------------- kernel 1: depthwise 3x3 + BN1 + exact GELU, build S ---------
__global__ __launch_bounds__(256) void k_dw(const float* __restrict__ x,
                                            const float* __restrict__ dw_w,
                                            const float* __restrict__ g1,
                                            const float* __restrict__ b1,
                                            const float* __restrict__ m1,
                                            const float* __restrict__ v1) {
    __shared__ float t[TH][TW];
    int bid = blockIdx.x;                 // RR*BB*CIN = 65536 blocks
    int c  = bid & 127;
    int bb = (bid >> 7) & 7;
    int r  = bid >> 10;
    int gh = r >> 3, gw = r & 7;
    int tid = threadIdx.x;

    const float* xp = x + (((size_t)(bb * CIN + c) * 256 + gh * TH) * 256 + gw * TW);
    #pragma unroll
    for (int p = tid; p < NPIX; p += 256) {
        int row = p >> 5, col = p & 31;
        t[row][col] = xp[(size_t)row * 256 + col];
    }

    float w[9];
    const float* wp = dw_w + (size_t)(r * CIN + c) * 9;
    #pragma unroll
    for (int i = 0; i < 9; i++) w[i] = wp[i];

    int rc = r * CIN + c;
    float rs = rsqrtf(v1[rc] + EPSV);
    float sc = g1[rc] * rs;
    float sh = b1[rc] - g1[rc] * m1[rc] * rs;

    __syncthreads();

    size_t base  = ((size_t)(r * KK + c)) * NN + (size_t)bb * NPIX;
    size_t basex = ((size_t)(r * KK + CIN + c)) * NN + (size_t)bb * NPIX;

    #pragma unroll
    for (int p = tid; p < NPIX; p += 256) {
        int row = p >> 5, col = p & 31;
        float s = 0.f;
        #pragma unroll
        for (int dr = -1; dr <= 1; dr++) {
            #pragma unroll
            for (int dc = -1; dc <= 1; dc++) {
                int rr2 = row + dr, cc2 = col + dc;
                float vv = (rr2 >= 0 && rr2 < TH && cc2 >= 0 && cc2 < TW) ? t[rr2][cc2] : 0.f;
                s = fmaf(vv, w[(dr + 1) * 3 + (dc + 1)], s);
            }
        }
        float yv = fmaf(s, sc, sh);
        float gv = yv * normcdff(yv);        // exact GELU: x * Phi(x)
        g_S[base + p]  = gv;
        g_S[basex + p] = t[row][col];
    }
}

// ---------------- kernel 2: per-region GEMM + bias + reassembly ---------------
// C[r][o][n] = sum_k W[r][o][k] * S[r][k][n] + bias[r][o]
// out[b][o][gh*32+prow][gw*32+pcol],  n = b*1024 + prow*32 + pcol
#define BM 128
#define BN 128
#define BKS 8

__global__ __launch_bounds__(256) void k_gemm(float* __restrict__ out) {
    __shared__ float As[BKS][BM + 4];
    __shared__ float Bs[BKS][BN];

    int r  = blockIdx.z;
    int m0 = blockIdx.y * BM;
    int n0 = blockIdx.x * BN;
    const float* A = g_W + (size_t)r * COUT * KK;
    const float* Bm = g_S + (size_t)r * KK * NN;

    int tid = threadIdx.x;
    int tx = tid & 15, ty = tid >> 4;

    // A-tile load mapping: row = tid>>1 (0..127), 4 consecutive k at (tid&1)*4
    int a_row = tid >> 1;
    int a_k4  = (tid & 1) * 4;
    // B-tile load mapping: krow = tid>>5 (0..7), 4 consecutive n at (tid&31)*4
    int b_kr  = tid >> 5;
    int b_n4  = (tid & 31) * 4;

    float acc[8][8];
    #pragma unroll
    for (int i = 0; i < 8; i++)
        #pragma unroll
        for (int j = 0; j < 8; j++) acc[i][j] = 0.f;

    for (int k0 = 0; k0 < KK; k0 += BKS) {
        float4 av = *(const float4*)&A[(size_t)(m0 + a_row) * KK + k0 + a_k4];
        As[a_k4 + 0][a_row] = av.x;
        As[a_k4 + 1][a_row] = av.y;
        As[a_k4 + 2][a_row] = av.z;
        As[a_k4 + 3][a_row] = av.w;
        float4 bv = *(const float4*)&Bm[(size_t)(k0 + b_kr) * NN + n0 + b_n4];
        *(float4*)&Bs[b_kr][b_n4] = bv;
        __syncthreads();

        #pragma unroll
        for (int kk = 0; kk < BKS; kk++) {
            float4 a0 = *(const float4*)&As[kk][ty * 8];
            float4 a1 = *(const float4*)&As[kk][ty * 8 + 4];
            float4 c0 = *(const float4*)&Bs[kk][tx * 8];
            float4 c1 = *(const float4*)&Bs[kk][tx * 8 + 4];
            float ar[8] = {a0.x, a0.y, a0.z, a0.w, a1.x, a1.y, a1.z, a1.w};
            float br[8] = {c0.x, c0.y, c0.z, c0.w, c1.x, c1.y, c1.z, c1.w};
            #pragma unroll
            for (int i = 0; i < 8; i++)
                #pragma unroll
                for (int j = 0; j < 8; j++)
                    acc[i][j] = fmaf(ar[i], br[j], acc[i][j]);
        }
        __syncthreads();
    }

    // epilogue: bias + scatter back into [B, COUT, 256, 256]
    int gh = r >> 3, gw = r & 7;
    int n_base = n0 + tx * 8;
    int b_idx  = n_base >> 10;
    int hw     = n_base & 1023;
    int prow   = hw >> 5, pcol = hw & 31;

    #pragma unroll
    for (int i = 0; i < 8; i++) {
        int mo = m0 + ty * 8 + i;
        float bi = g_bias[r * COUT + mo];
        size_t ooff = (((size_t)(b_idx * COUT + mo) * 256 + gh * TH + prow) * 256 + gw * TW + pcol);
        float4 v0 = make_float4(acc[i][0] + bi, acc[i][1] + bi, acc[i][2] + bi, acc[i][3] + bi);
        float4 v1 = make_float4(acc[i][4] + bi, acc[i][5] + bi, acc[i][6] + bi, acc[i][7] + bi);
        *(float4*)&out[ooff]     = v0;
        *(float4*)&out[ooff + 4] = v1;
    }
}

// ---------------- launch ------------------------------------------------------
extern "C" void kernel_launch(void* const* d_in, const int* in_sizes, int n_in,
                              void* d_out, int out_size) {
    const float* x     = (const float*)d_in[0];
    const float* dw_w  = (const float*)d_in[1];
    const float* bn1_g = (const float*)d_in[2];
    const float* bn1_b = (const float*)d_in[3];
    const float* bn1_m = (const float*)d_in[4];
    const float* bn1_v = (const float*)d_in[5];
    const float* pw_w  = (const float*)d_in[6];
    const float* bn2_g = (const float*)d_in[7];
    const float* bn2_b = (const float*)d_in[8];
    const float* bn2_m = (const float*)d_in[9];
    const float* bn2_v = (const float*)d_in[10];
    const float* res_w = (const float*)d_in[11];
    float* out = (float*)d_out;

    // fold BN2 into GEMM weights + bias
    k_prep<<<(RR * COUT * KK) / 256, 256>>>(pw_w, res_w, bn2_g, bn2_b, bn2_m, bn2_v);
    // depthwise + BN1 + GELU, build stacked operand S
    k_dw<<<RR * BB * CIN, 256>>>(x, dw_w, bn1_g, bn1_b, bn1_m, bn1_v);
    // batched per-region GEMM + bias + reassembly
    dim3 grid(NN / BN, COUT / BM, RR);
    k_gemm<<<grid, 256>>>(out);
}

// round 6
// speedup vs baseline: 1.7449x; 1.7444x over previous
#include <cuda_runtime.h>
#include <cuda_bf16.h>
#include <cstdint>

#define GH 8
#define GW 8
#define RR 64
#define BB 8
#define CIN 128
#define COUT 256
#define NPIX 1024
#define NN 8192           // GEMM N per region (BB*NPIX)
#define KP 512            // packed K': [gelu_hi(128)|x_hi(128)|gelu_lo(128)|x_lo(128)]
#define EPSV 1e-5f

// ---------------- scratch (device globals; no runtime allocation) -------------
__device__ __nv_bfloat16 g_Sb[(size_t)RR * NN * KP];     // 512 MB
__device__ __nv_bfloat16 g_Wb[(size_t)RR * COUT * KP];   // 16 MB
__device__ float g_bias[RR * COUT];

// ---------------- helpers -----------------------------------------------------
__device__ __forceinline__ uint32_t smem_u32(const void* p) {
    uint32_t a;
    asm("{ .reg .u64 t; cvta.to.shared.u64 t, %1; cvt.u32.u64 %0, t; }" : "=r"(a) : "l"(p));
    return a;
}
__device__ __forceinline__ void cpa16(uint32_t dst, const void* src) {
    asm volatile("cp.async.cg.shared.global [%0], [%1], 16;" :: "r"(dst), "l"(src) : "memory");
}
#define LDSM4(d, addr)                                                          \
    asm volatile("ldmatrix.sync.aligned.m8n8.x4.shared.b16 {%0,%1,%2,%3}, [%4];" \
                 : "=r"((d)[0]), "=r"((d)[1]), "=r"((d)[2]), "=r"((d)[3])        \
                 : "r"(addr))
#define MMA(c, a, b0v, b1v)                                                      \
    asm volatile("mma.sync.aligned.m16n8k16.row.col.f32.bf16.bf16.f32 "          \
                 "{%0,%1,%2,%3},{%4,%5,%6,%7},{%8,%9},{%0,%1,%2,%3};"            \
                 : "+f"((c)[0]), "+f"((c)[1]), "+f"((c)[2]), "+f"((c)[3])        \
                 : "r"((a)[0]), "r"((a)[1]), "r"((a)[2]), "r"((a)[3]),           \
                   "r"(b0v), "r"(b1v))

// ---------------- kernel 0: fold BN2 into bf16 hi/lo weights ------------------
__global__ __launch_bounds__(256) void k_prep(const float* __restrict__ pw_w,
                                              const float* __restrict__ res_w,
                                              const float* __restrict__ g2,
                                              const float* __restrict__ b2,
                                              const float* __restrict__ m2,
                                              const float* __restrict__ v2) {
    int idx = blockIdx.x * 256 + threadIdx.x;      // RR*COUT*256
    int r = idx >> 16;
    int rem = idx & 65535;
    int o = rem >> 8;
    int k = rem & 255;
    int ro = r * COUT + o;
    float rs = rsqrtf(v2[ro] + EPSV);
    float scv = g2[ro] * rs;
    float wv = (k < CIN) ? scv * pw_w[(size_t)ro * CIN + k]
                         : res_w[(size_t)ro * CIN + (k - CIN)];
    __nv_bfloat16 hi = __float2bfloat16(wv);
    __nv_bfloat16 lo = __float2bfloat16(wv - __bfloat162float(hi));
    size_t base = (size_t)ro * KP;
    g_Wb[base + k] = hi;
    g_Wb[base + 256 + k] = lo;
    if (k == 0) g_bias[ro] = b2[ro] - g2[ro] * m2[ro] * rs;
}

// ---------------- kernel 1: dw 3x3 + BN1 + GELU -> S[r][n][k'] bf16 hi/lo -----
#define CSTR 205   // 6*34 + 1 (odd -> conflict-free channel stride)
__global__ __launch_bounds__(512) void k_dw(const float* __restrict__ x,
                                            const float* __restrict__ dw_w,
                                            const float* __restrict__ g1,
                                            const float* __restrict__ b1,
                                            const float* __restrict__ m1,
                                            const float* __restrict__ v1) {
    extern __shared__ float sx[];  // [128 ch][6 rows][34 cols], stride CSTR
    int bxx = blockIdx.x;
    int chunk = bxx & 7, bb = (bxx >> 3) & 7, r = bxx >> 6;
    int gh = r >> 3, gw = r & 7;
    int tid = threadIdx.x;
    int r0 = chunk * 4;

    for (int i = tid; i < 128 * CSTR; i += 512) sx[i] = 0.f;
    __syncthreads();
    for (int i = tid; i < 6 * 128 * 32; i += 512) {
        int rr = i >> 12;
        int c = (i >> 5) & 127;
        int col = i & 31;
        int g = r0 - 1 + rr;
        if (g >= 0 && g < 32)
            sx[c * CSTR + rr * 34 + 1 + col] =
                x[(((size_t)(bb * CIN + c)) * 256 + gh * 32 + g) * 256 + gw * 32 + col];
    }
    __syncthreads();

    int c = tid & 127, ps = tid >> 7;
    int rc = r * CIN + c;
    float w9[9];
    const float* wp = dw_w + (size_t)rc * 9;
#pragma unroll
    for (int i = 0; i < 9; i++) w9[i] = wp[i];
    float rs = rsqrtf(v1[rc] + EPSV);
    float sc = g1[rc] * rs;
    float sh = b1[rc] - g1[rc] * m1[rc] * rs;

    int row = r0 + ps;
    const float* sb = sx + c * CSTR + ps * 34;
    __nv_bfloat16* Sp = g_Sb + ((size_t)r * NN + (size_t)bb * NPIX + (size_t)row * 32) * KP;

#pragma unroll 4
    for (int col = 0; col < 32; col++) {
        float acc = 0.f;
#pragma unroll
        for (int dr = 0; dr < 3; dr++)
#pragma unroll
            for (int dc = 0; dc < 3; dc++)
                acc = fmaf(sb[dr * 34 + col + dc], w9[dr * 3 + dc], acc);
        float yv = fmaf(acc, sc, sh);
        float gv = yv * normcdff(yv);               // exact GELU
        float xv = sb[34 + col + 1];
        __nv_bfloat16 gH = __float2bfloat16(gv);
        __nv_bfloat16 gL = __float2bfloat16(gv - __bfloat162float(gH));
        __nv_bfloat16 xH = __float2bfloat16(xv);
        __nv_bfloat16 xL = __float2bfloat16(xv - __bfloat162float(xH));
        __nv_bfloat16* o = Sp + (size_t)col * KP;
        o[c] = gH;
        o[128 + c] = xH;
        o[256 + c] = gL;
        o[384 + c] = xL;
    }
}

// ---------------- kernel 2: warp-MMA bf16-split GEMM + epilogue ---------------
// CTA tile 128x128, K-chunk 64, 3-term split. SMEM per stage (bf16 elems):
//   A_hi @0, A_lo @9216, B_hi @18432, B_lo @27648; row stride 72 (144B).
#define STG_E 36864
#define STG_B (STG_E * 2)

__global__ __launch_bounds__(256, 1) void k_gemm(float* __restrict__ out) {
    extern __shared__ __nv_bfloat16 smb[];
    uint32_t sbase = smem_u32(smb);
    int tid = threadIdx.x, lane = tid & 31, wid = tid >> 5;
    int wm = wid & 1, wn = wid >> 1;                 // warp tile: 64 (m) x 32 (n)
    int n0 = blockIdx.x * 128, m0 = blockIdx.y * 128, r = blockIdx.z;
    int gh = r >> 3, gw = r & 7;

    const __nv_bfloat16* Wp = g_Wb + (size_t)(r * COUT + m0) * KP;
    const __nv_bfloat16* Sp = g_Sb + ((size_t)r * NN + n0) * KP;

    float acc[4][4][4];
#pragma unroll
    for (int i = 0; i < 4; i++)
#pragma unroll
        for (int j = 0; j < 4; j++)
#pragma unroll
            for (int t = 0; t < 4; t++) acc[i][j][t] = 0.f;

    // cp.async load of one stage (both operands, hi+lo planes)
    auto load_stage = [&](int s, int kc) {
        uint32_t st = sbase + (uint32_t)s * STG_B;
#pragma unroll
        for (int i = tid; i < 2048; i += 256) {      // A: 2 planes x 128 rows x 8 segs
            int pl = i >> 10, rw = (i >> 3) & 127, sg = i & 7;
            cpa16(st + 2u * (pl * 9216 + rw * 72 + sg * 8),
                  Wp + (size_t)rw * KP + pl * 256 + kc + sg * 8);
        }
#pragma unroll
        for (int i = tid; i < 2048; i += 256) {      // B
            int pl = i >> 10, rw = (i >> 3) & 127, sg = i & 7;
            cpa16(st + 2u * (18432 + pl * 9216 + rw * 72 + sg * 8),
                  Sp + (size_t)rw * KP + pl * 256 + kc + sg * 8);
        }
        asm volatile("cp.async.commit_group;" ::: "memory");
    };

    int lrow = lane & 15, lc8 = (lane >> 4) * 8;     // ldmatrix address split
    load_stage(0, 0);

    for (int c = 0; c < 4; c++) {
        if (c < 3) load_stage((c + 1) & 1, (c + 1) * 64);
        if (c < 3) asm volatile("cp.async.wait_group 1;" ::: "memory");
        else       asm volatile("cp.async.wait_group 0;" ::: "memory");
        __syncthreads();

        uint32_t st = sbase + (uint32_t)(c & 1) * STG_B;
        uint32_t aA = st + 2u * ((wm * 64 + lrow) * 72 + lc8);
        uint32_t aB = st + 2u * (18432 + (wn * 32 + lrow) * 72 + lc8);

#pragma unroll
        for (int ks = 0; ks < 4; ks++) {
            uint32_t ko = 2u * (ks * 16);
            uint32_t ah[4][4], al[4][4], bh[2][4], bl[2][4];
#pragma unroll
            for (int mt = 0; mt < 4; mt++) LDSM4(ah[mt], aA + 2u * (mt * 16 * 72) + ko);
#pragma unroll
            for (int p = 0; p < 2; p++)    LDSM4(bh[p], aB + 2u * (p * 16 * 72) + ko);
            // term 0: Ah * Bh
#pragma unroll
            for (int mt = 0; mt < 4; mt++)
#pragma unroll
                for (int nt = 0; nt < 4; nt++)
                    MMA(acc[mt][nt], ah[mt], bh[nt >> 1][nt & 1], bh[nt >> 1][2 + (nt & 1)]);
            // term 1: Al * Bh
#pragma unroll
            for (int mt = 0; mt < 4; mt++) LDSM4(al[mt], aA + 2u * (9216 + mt * 16 * 72) + ko);
#pragma unroll
            for (int mt = 0; mt < 4; mt++)
#pragma unroll
                for (int nt = 0; nt < 4; nt++)
                    MMA(acc[mt][nt], al[mt], bh[nt >> 1][nt & 1], bh[nt >> 1][2 + (nt & 1)]);
            // term 2: Ah * Bl
#pragma unroll
            for (int p = 0; p < 2; p++)    LDSM4(bl[p], aB + 2u * (9216 + p * 16 * 72) + ko);
#pragma unroll
            for (int mt = 0; mt < 4; mt++)
#pragma unroll
                for (int nt = 0; nt < 4; nt++)
                    MMA(acc[mt][nt], ah[mt], bl[nt >> 1][nt & 1], bl[nt >> 1][2 + (nt & 1)]);
        }
        __syncthreads();
    }

    // ---- epilogue: bias + scatter to [B, COUT, 256, 256] ----
    int qrow = lane >> 2, qcol = (lane & 3) * 2;
#pragma unroll
    for (int mt = 0; mt < 4; mt++) {
        int mrow = m0 + wm * 64 + mt * 16 + qrow;
        float bi0 = g_bias[r * COUT + mrow];
        float bi1 = g_bias[r * COUT + mrow + 8];
#pragma unroll
        for (int nt = 0; nt < 4; nt++) {
            int nidx = n0 + wn * 32 + nt * 8 + qcol;
            int b = nidx >> 10, hw = nidx & 1023;
            int prow = hw >> 5, pcol = hw & 31;
            size_t off0 = (((size_t)(b * COUT + mrow) * 256 + gh * 32 + prow) * 256 +
                           gw * 32 + pcol);
            size_t off1 = off0 + (size_t)8 * 65536;          // mrow+8
            float2 v0 = make_float2(acc[mt][nt][0] + bi0, acc[mt][nt][1] + bi0);
            float2 v1 = make_float2(acc[mt][nt][2] + bi1, acc[mt][nt][3] + bi1);
            *(float2*)&out[off0] = v0;
            *(float2*)&out[off1] = v1;
        }
    }
}

// ---------------- launch ------------------------------------------------------
extern "C" void kernel_launch(void* const* d_in, const int* in_sizes, int n_in,
                              void* d_out, int out_size) {
    const float* x     = (const float*)d_in[0];
    const float* dw_w  = (const float*)d_in[1];
    const float* bn1_g = (const float*)d_in[2];
    const float* bn1_b = (const float*)d_in[3];
    const float* bn1_m = (const float*)d_in[4];
    const float* bn1_v = (const float*)d_in[5];
    const float* pw_w  = (const float*)d_in[6];
    const float* bn2_g = (const float*)d_in[7];
    const float* bn2_b = (const float*)d_in[8];
    const float* bn2_m = (const float*)d_in[9];
    const float* bn2_v = (const float*)d_in[10];
    const float* res_w = (const float*)d_in[11];
    float* out = (float*)d_out;

    cudaFuncSetAttribute(k_gemm, cudaFuncAttributeMaxDynamicSharedMemorySize,
                         2 * STG_B);
    cudaFuncSetAttribute(k_dw, cudaFuncAttributeMaxDynamicSharedMemorySize,
                         128 * CSTR * 4);

    k_prep<<<(RR * COUT * 256) / 256, 256>>>(pw_w, res_w, bn2_g, bn2_b, bn2_m, bn2_v);
    k_dw<<<RR * BB * 8, 512, 128 * CSTR * 4>>>(x, dw_w, bn1_g, bn1_b, bn1_m, bn1_v);
    dim3 grid(NN / 128, COUT / 128, RR);
    k_gemm<<<grid, 256, 2 * STG_B>>>(out);
}

// round 7
// speedup vs baseline: 1.7871x; 1.0242x over previous
#include <cuda_runtime.h>
#include <cuda_bf16.h>
#include <cstdint>

#define GH 8
#define GW 8
#define RR 64
#define BB 8
#define CIN 128
#define COUT 256
#define NPIX 1024
#define NN 8192           // GEMM N per region (BB*NPIX)
#define KP 512            // packed K': [gelu_hi(128)|x_hi(128)|gelu_lo(128)|x_lo(128)]
#define EPSV 1e-5f

// ---------------- scratch (device globals; no runtime allocation) -------------
__device__ __nv_bfloat16 g_Sb[(size_t)RR * NN * KP];     // 512 MB
__device__ __nv_bfloat16 g_Wb[(size_t)RR * COUT * KP];   // 16 MB
__device__ float g_bias[RR * COUT];

// ---------------- helpers -----------------------------------------------------
__device__ __forceinline__ uint32_t smem_u32(const void* p) {
    uint32_t a;
    asm("{ .reg .u64 t; cvta.to.shared.u64 t, %1; cvt.u32.u64 %0, t; }" : "=r"(a) : "l"(p));
    return a;
}
__device__ __forceinline__ void cpa16(uint32_t dst, const void* src) {
    asm volatile("cp.async.cg.shared.global [%0], [%1], 16;" :: "r"(dst), "l"(src) : "memory");
}
#define LDSM4(d, addr)                                                          \
    asm volatile("ldmatrix.sync.aligned.m8n8.x4.shared.b16 {%0,%1,%2,%3}, [%4];" \
                 : "=r"((d)[0]), "=r"((d)[1]), "=r"((d)[2]), "=r"((d)[3])        \
                 : "r"(addr))
#define MMA(c, a, b0v, b1v)                                                      \
    asm volatile("mma.sync.aligned.m16n8k16.row.col.f32.bf16.bf16.f32 "          \
                 "{%0,%1,%2,%3},{%4,%5,%6,%7},{%8,%9},{%0,%1,%2,%3};"            \
                 : "+f"((c)[0]), "+f"((c)[1]), "+f"((c)[2]), "+f"((c)[3])        \
                 : "r"((a)[0]), "r"((a)[1]), "r"((a)[2]), "r"((a)[3]),           \
                   "r"(b0v), "r"(b1v))

// ---------------- kernel 0: fold BN2 into bf16 hi/lo weights ------------------
__global__ __launch_bounds__(256) void k_prep(const float* __restrict__ pw_w,
                                              const float* __restrict__ res_w,
                                              const float* __restrict__ g2,
                                              const float* __restrict__ b2,
                                              const float* __restrict__ m2,
                                              const float* __restrict__ v2) {
    int idx = blockIdx.x * 256 + threadIdx.x;      // RR*COUT*256
    int r = idx >> 16;
    int rem = idx & 65535;
    int o = rem >> 8;
    int k = rem & 255;
    int ro = r * COUT + o;
    float rs = rsqrtf(v2[ro] + EPSV);
    float scv = g2[ro] * rs;
    float wv = (k < CIN) ? scv * pw_w[(size_t)ro * CIN + k]
                         : res_w[(size_t)ro * CIN + (k - CIN)];
    __nv_bfloat16 hi = __float2bfloat16(wv);
    __nv_bfloat16 lo = __float2bfloat16(wv - __bfloat162float(hi));
    size_t base = (size_t)ro * KP;
    g_Wb[base + k] = hi;
    g_Wb[base + 256 + k] = lo;
    if (k == 0) g_bias[ro] = b2[ro] - g2[ro] * m2[ro] * rs;
}

// ---------------- kernel 1: dw 3x3 + BN1 + GELU -> S[r][n][k'] bf16 hi/lo -----
#define CSTR 205   // 6*34 + 1 (odd -> conflict-free channel stride)
__global__ __launch_bounds__(512) void k_dw(const float* __restrict__ x,
                                            const float* __restrict__ dw_w,
                                            const float* __restrict__ g1,
                                            const float* __restrict__ b1,
                                            const float* __restrict__ m1,
                                            const float* __restrict__ v1) {
    extern __shared__ float sx[];  // [128 ch][6 rows][34 cols], stride CSTR
    int bxx = blockIdx.x;
    int chunk = bxx & 7, bb = (bxx >> 3) & 7, r = bxx >> 6;
    int gh = r >> 3, gw = r & 7;
    int tid = threadIdx.x;
    int r0 = chunk * 4;

    for (int i = tid; i < 128 * CSTR; i += 512) sx[i] = 0.f;
    __syncthreads();
    for (int i = tid; i < 6 * 128 * 32; i += 512) {
        int rr = i >> 12;
        int c = (i >> 5) & 127;
        int col = i & 31;
        int g = r0 - 1 + rr;
        if (g >= 0 && g < 32)
            sx[c * CSTR + rr * 34 + 1 + col] =
                x[(((size_t)(bb * CIN + c)) * 256 + gh * 32 + g) * 256 + gw * 32 + col];
    }
    __syncthreads();

    int c = tid & 127, ps = tid >> 7;
    int rc = r * CIN + c;
    float w9[9];
    const float* wp = dw_w + (size_t)rc * 9;
#pragma unroll
    for (int i = 0; i < 9; i++) w9[i] = wp[i];
    float rs = rsqrtf(v1[rc] + EPSV);
    float sc = g1[rc] * rs;
    float sh = b1[rc] - g1[rc] * m1[rc] * rs;

    int row = r0 + ps;
    const float* sb = sx + c * CSTR + ps * 34;
    __nv_bfloat16* Sp = g_Sb + ((size_t)r * NN + (size_t)bb * NPIX + (size_t)row * 32) * KP;

#pragma unroll 4
    for (int col = 0; col < 32; col++) {
        float acc = 0.f;
#pragma unroll
        for (int dr = 0; dr < 3; dr++)
#pragma unroll
            for (int dc = 0; dc < 3; dc++)
                acc = fmaf(sb[dr * 34 + col + dc], w9[dr * 3 + dc], acc);
        float yv = fmaf(acc, sc, sh);
        float gv = yv * normcdff(yv);               // exact GELU
        float xv = sb[34 + col + 1];
        __nv_bfloat16 gH = __float2bfloat16(gv);
        __nv_bfloat16 gL = __float2bfloat16(gv - __bfloat162float(gH));
        __nv_bfloat16 xH = __float2bfloat16(xv);
        __nv_bfloat16 xL = __float2bfloat16(xv - __bfloat162float(xH));
        __nv_bfloat16* o = Sp + (size_t)col * KP;
        o[c] = gH;
        o[128 + c] = xH;
        o[256 + c] = gL;
        o[384 + c] = xL;
    }
}

// ---------------- kernel 2: warp-MMA bf16-split GEMM + epilogue ---------------
// CTA tile 128x128, 512 threads / 16 warps (warp tile 32x32), K-chunk 64,
// 3-term split. SMEM per stage (bf16 elems): A_hi @0, A_lo @9216,
// B_hi @18432, B_lo @27648; row stride 72 (144B).
#define STG_E 36864
#define STG_B (STG_E * 2)

__global__ __launch_bounds__(512, 1) void k_gemm(float* __restrict__ out) {
    extern __shared__ __nv_bfloat16 smb[];
    uint32_t sbase = smem_u32(smb);
    int tid = threadIdx.x, lane = tid & 31, wid = tid >> 5;
    int wm = wid & 3, wn = wid >> 2;                 // 4x4 warp grid, 32x32 warp tile
    int n0 = blockIdx.x * 128, m0 = blockIdx.y * 128, r = blockIdx.z;
    int gh = r >> 3, gw = r & 7;

    const __nv_bfloat16* Wp = g_Wb + (size_t)(r * COUT + m0) * KP;
    const __nv_bfloat16* Sp = g_Sb + ((size_t)r * NN + n0) * KP;

    float acc[2][4][4];
#pragma unroll
    for (int i = 0; i < 2; i++)
#pragma unroll
        for (int j = 0; j < 4; j++)
#pragma unroll
            for (int t = 0; t < 4; t++) acc[i][j][t] = 0.f;

    // cp.async load of one stage (both operands, hi+lo planes)
    auto load_stage = [&](int s, int kc) {
        uint32_t st = sbase + (uint32_t)s * STG_B;
#pragma unroll
        for (int i = tid; i < 2048; i += 512) {      // A: 2 planes x 128 rows x 8 segs
            int pl = i >> 10, rw = (i >> 3) & 127, sg = i & 7;
            cpa16(st + 2u * (pl * 9216 + rw * 72 + sg * 8),
                  Wp + (size_t)rw * KP + pl * 256 + kc + sg * 8);
        }
#pragma unroll
        for (int i = tid; i < 2048; i += 512) {      // B
            int pl = i >> 10, rw = (i >> 3) & 127, sg = i & 7;
            cpa16(st + 2u * (18432 + pl * 9216 + rw * 72 + sg * 8),
                  Sp + (size_t)rw * KP + pl * 256 + kc + sg * 8);
        }
        asm volatile("cp.async.commit_group;" ::: "memory");
    };

    int lrow = lane & 15, lc8 = (lane >> 4) * 8;     // ldmatrix address split
    load_stage(0, 0);

    for (int c = 0; c < 4; c++) {
        if (c < 3) load_stage((c + 1) & 1, (c + 1) * 64);
        if (c < 3) asm volatile("cp.async.wait_group 1;" ::: "memory");
        else       asm volatile("cp.async.wait_group 0;" ::: "memory");
        __syncthreads();

        uint32_t st = sbase + (uint32_t)(c & 1) * STG_B;
        uint32_t aA = st + 2u * ((wm * 32 + lrow) * 72 + lc8);
        uint32_t aB = st + 2u * (18432 + (wn * 32 + lrow) * 72 + lc8);

#pragma unroll
        for (int ks = 0; ks < 4; ks++) {
            uint32_t ko = 2u * (ks * 16);
            uint32_t ah[2][4], al[2][4], bh[2][4], bl[2][4];
#pragma unroll
            for (int mt = 0; mt < 2; mt++) LDSM4(ah[mt], aA + 2u * (mt * 16 * 72) + ko);
#pragma unroll
            for (int mt = 0; mt < 2; mt++) LDSM4(al[mt], aA + 2u * (9216 + mt * 16 * 72) + ko);
#pragma unroll
            for (int p = 0; p < 2; p++)    LDSM4(bh[p], aB + 2u * (p * 16 * 72) + ko);
#pragma unroll
            for (int p = 0; p < 2; p++)    LDSM4(bl[p], aB + 2u * (9216 + p * 16 * 72) + ko);
            // term 0: Ah * Bh
#pragma unroll
            for (int mt = 0; mt < 2; mt++)
#pragma unroll
                for (int nt = 0; nt < 4; nt++)
                    MMA(acc[mt][nt], ah[mt], bh[nt >> 1][nt & 1], bh[nt >> 1][2 + (nt & 1)]);
            // term 1: Al * Bh
#pragma unroll
            for (int mt = 0; mt < 2; mt++)
#pragma unroll
                for (int nt = 0; nt < 4; nt++)
                    MMA(acc[mt][nt], al[mt], bh[nt >> 1][nt & 1], bh[nt >> 1][2 + (nt & 1)]);
            // term 2: Ah * Bl
#pragma unroll
            for (int mt = 0; mt < 2; mt++)
#pragma unroll
                for (int nt = 0; nt < 4; nt++)
                    MMA(acc[mt][nt], ah[mt], bl[nt >> 1][nt & 1], bl[nt >> 1][2 + (nt & 1)]);
        }
        __syncthreads();
    }

    // ---- epilogue: bias + scatter to [B, COUT, 256, 256] ----
    int qrow = lane >> 2, qcol = (lane & 3) * 2;
#pragma unroll
    for (int mt = 0; mt < 2; mt++) {
        int mrow = m0 + wm * 32 + mt * 16 + qrow;
        float bi0 = g_bias[r * COUT + mrow];
        float bi1 = g_bias[r * COUT + mrow + 8];
#pragma unroll
        for (int nt = 0; nt < 4; nt++) {
            int nidx = n0 + wn * 32 + nt * 8 + qcol;
            int b = nidx >> 10, hw = nidx & 1023;
            int prow = hw >> 5, pcol = hw & 31;
            size_t off0 = (((size_t)(b * COUT + mrow) * 256 + gh * 32 + prow) * 256 +
                           gw * 32 + pcol);
            size_t off1 = off0 + (size_t)8 * 65536;          // mrow+8
            float2 v0 = make_float2(acc[mt][nt][0] + bi0, acc[mt][nt][1] + bi0);
            float2 v1 = make_float2(acc[mt][nt][2] + bi1, acc[mt][nt][3] + bi1);
            *(float2*)&out[off0] = v0;
            *(float2*)&out[off1] = v1;
        }
    }
}

// ---------------- launch ------------------------------------------------------
extern "C" void kernel_launch(void* const* d_in, const int* in_sizes, int n_in,
                              void* d_out, int out_size) {
    const float* x     = (const float*)d_in[0];
    const float* dw_w  = (const float*)d_in[1];
    const float* bn1_g = (const float*)d_in[2];
    const float* bn1_b = (const float*)d_in[3];
    const float* bn1_m = (const float*)d_in[4];
    const float* bn1_v = (const float*)d_in[5];
    const float* pw_w  = (const float*)d_in[6];
    const float* bn2_g = (const float*)d_in[7];
    const float* bn2_b = (const float*)d_in[8];
    const float* bn2_m = (const float*)d_in[9];
    const float* bn2_v = (const float*)d_in[10];
    const float* res_w = (const float*)d_in[11];
    float* out = (float*)d_out;

    cudaFuncSetAttribute(k_gemm, cudaFuncAttributeMaxDynamicSharedMemorySize,
                         2 * STG_B);
    cudaFuncSetAttribute(k_dw, cudaFuncAttributeMaxDynamicSharedMemorySize,
                         128 * CSTR * 4);

    k_prep<<<(RR * COUT * 256) / 256, 256>>>(pw_w, res_w, bn2_g, bn2_b, bn2_m, bn2_v);
    k_dw<<<RR * BB * 8, 512, 128 * CSTR * 4>>>(x, dw_w, bn1_g, bn1_b, bn1_m, bn1_v);
    dim3 grid(NN / 128, COUT / 128, RR);
    k_gemm<<<grid, 512, 2 * STG_B>>>(out);
}

// round 8
// speedup vs baseline: 2.4014x; 1.3437x over previous
#include <cuda_runtime.h>
#include <cuda_bf16.h>
#include <cuda_fp16.h>
#include <cstdint>

#define GH 8
#define GW 8
#define RR 64
#define BB 8
#define CIN 128
#define COUT 256
#define NPIX 1024
#define NN 8192           // GEMM N per region (BB*NPIX)
#define KP2 256           // packed K: [gelu(128) | x(128)] fp16
#define EPSV 1e-5f

// ---------------- scratch (device globals; no runtime allocation) -------------
__device__ __half g_Sh[(size_t)RR * NN * KP2];            // 256 MB
__device__ __half g_Wh[(size_t)RR * COUT * 512];          // 16 MB: [hi(256) | lo(256)]
__device__ float g_bias[RR * COUT];

// ---------------- helpers -----------------------------------------------------
__device__ __forceinline__ uint32_t smem_u32(const void* p) {
    uint32_t a;
    asm("{ .reg .u64 t; cvta.to.shared.u64 t, %1; cvt.u32.u64 %0, t; }" : "=r"(a) : "l"(p));
    return a;
}
__device__ __forceinline__ void cpa16(uint32_t dst, const void* src) {
    asm volatile("cp.async.cg.shared.global [%0], [%1], 16;" :: "r"(dst), "l"(src) : "memory");
}
#define LDSM4(d, addr)                                                          \
    asm volatile("ldmatrix.sync.aligned.m8n8.x4.shared.b16 {%0,%1,%2,%3}, [%4];" \
                 : "=r"((d)[0]), "=r"((d)[1]), "=r"((d)[2]), "=r"((d)[3])        \
                 : "r"(addr))
#define MMAH(c, a, b0v, b1v)                                                     \
    asm volatile("mma.sync.aligned.m16n8k16.row.col.f32.f16.f16.f32 "            \
                 "{%0,%1,%2,%3},{%4,%5,%6,%7},{%8,%9},{%0,%1,%2,%3};"            \
                 : "+f"((c)[0]), "+f"((c)[1]), "+f"((c)[2]), "+f"((c)[3])        \
                 : "r"((a)[0]), "r"((a)[1]), "r"((a)[2]), "r"((a)[3]),           \
                   "r"(b0v), "r"(b1v))

// ---------------- kernel 0: fold BN2 into fp16 hi/lo weights ------------------
__global__ __launch_bounds__(256) void k_prep(const float* __restrict__ pw_w,
                                              const float* __restrict__ res_w,
                                              const float* __restrict__ g2,
                                              const float* __restrict__ b2,
                                              const float* __restrict__ m2,
                                              const float* __restrict__ v2) {
    int idx = blockIdx.x * 256 + threadIdx.x;      // RR*COUT*256
    int r = idx >> 16;
    int rem = idx & 65535;
    int o = rem >> 8;
    int k = rem & 255;
    int ro = r * COUT + o;
    float rs = rsqrtf(v2[ro] + EPSV);
    float scv = g2[ro] * rs;
    float wv = (k < CIN) ? scv * pw_w[(size_t)ro * CIN + k]
                         : res_w[(size_t)ro * CIN + (k - CIN)];
    __half hi = __float2half(wv);
    __half lo = __float2half(wv - __half2float(hi));
    size_t base = (size_t)ro * 512;
    g_Wh[base + k] = hi;
    g_Wh[base + 256 + k] = lo;
    if (k == 0) g_bias[ro] = b2[ro] - g2[ro] * m2[ro] * rs;
}

// ---------------- kernel 1: dw 3x3 + BN1 + GELU -> S[r][n][k] fp16 ------------
#define CSTR 205   // 6*34 + 1 (odd -> conflict-free channel stride)
__global__ __launch_bounds__(512) void k_dw(const float* __restrict__ x,
                                            const float* __restrict__ dw_w,
                                            const float* __restrict__ g1,
                                            const float* __restrict__ b1,
                                            const float* __restrict__ m1,
                                            const float* __restrict__ v1) {
    extern __shared__ float sx[];  // [128 ch][6 rows][34 cols], stride CSTR
    int bxx = blockIdx.x;
    int chunk = bxx & 7, bb = (bxx >> 3) & 7, r = bxx >> 6;
    int gh = r >> 3, gw = r & 7;
    int tid = threadIdx.x;
    int r0 = chunk * 4;

    for (int i = tid; i < 128 * CSTR; i += 512) sx[i] = 0.f;
    __syncthreads();
    for (int i = tid; i < 6 * 128 * 32; i += 512) {
        int rr = i >> 12;
        int c = (i >> 5) & 127;
        int col = i & 31;
        int g = r0 - 1 + rr;
        if (g >= 0 && g < 32)
            sx[c * CSTR + rr * 34 + 1 + col] =
                x[(((size_t)(bb * CIN + c)) * 256 + gh * 32 + g) * 256 + gw * 32 + col];
    }
    __syncthreads();

    int c = tid & 127, ps = tid >> 7;
    int rc = r * CIN + c;
    float w9[9];
    const float* wp = dw_w + (size_t)rc * 9;
#pragma unroll
    for (int i = 0; i < 9; i++) w9[i] = wp[i];
    float rs = rsqrtf(v1[rc] + EPSV);
    float sc = g1[rc] * rs;
    float sh = b1[rc] - g1[rc] * m1[rc] * rs;

    int row = r0 + ps;
    const float* sb = sx + c * CSTR + ps * 34;
    __half* Sp = g_Sh + ((size_t)r * NN + (size_t)bb * NPIX + (size_t)row * 32) * KP2;

#pragma unroll 4
    for (int col = 0; col < 32; col++) {
        float acc = 0.f;
#pragma unroll
        for (int dr = 0; dr < 3; dr++)
#pragma unroll
            for (int dc = 0; dc < 3; dc++)
                acc = fmaf(sb[dr * 34 + col + dc], w9[dr * 3 + dc], acc);
        float yv = fmaf(acc, sc, sh);
        float gv = yv * normcdff(yv);               // exact GELU
        float xv = sb[34 + col + 1];
        __half* o = Sp + (size_t)col * KP2;
        o[c] = __float2half(gv);
        o[128 + c] = __float2half(xv);
    }
}

// ---------------- kernel 2: fp16 2-term warp-MMA GEMM + epilogue --------------
// CTA tile 128m x 256n, 512 threads / 16 warps (warp tile 32x64), K-chunk 64.
// SMEM per stage (halfs): A_hi @0 (128x72), A_lo @9216, B @18432 (256x72).
#define STG_E 36864
#define STG_B (STG_E * 2)          // 73728 bytes/stage

__global__ __launch_bounds__(512, 1) void k_gemm(float* __restrict__ out) {
    extern __shared__ __half smb[];
    uint32_t sbase = smem_u32(smb);
    int tid = threadIdx.x, lane = tid & 31, wid = tid >> 5;
    int wm = wid & 3, wn = wid >> 2;                 // 4x4 warp grid; warp = 32m x 64n
    int m0 = blockIdx.x * 128, n0 = blockIdx.y * 256, r = blockIdx.z;
    int gh = r >> 3, gw = r & 7;

    const __half* Wp = g_Wh + (size_t)(r * COUT + m0) * 512;
    const __half* Sp = g_Sh + ((size_t)r * NN + n0) * KP2;

    float acc[2][8][4];
#pragma unroll
    for (int i = 0; i < 2; i++)
#pragma unroll
        for (int j = 0; j < 8; j++)
#pragma unroll
            for (int t = 0; t < 4; t++) acc[i][j][t] = 0.f;

    // cp.async load of one stage: A hi+lo planes (128x64 each) + B (256x64)
    auto load_stage = [&](int s, int kc) {
        uint32_t st = sbase + (uint32_t)s * STG_B;
#pragma unroll
        for (int i = tid; i < 2048; i += 512) {      // A: 2 planes x 128 rows x 8 segs
            int pl = i >> 10, rw = (i >> 3) & 127, sg = i & 7;
            cpa16(st + 2u * (pl * 9216 + rw * 72 + sg * 8),
                  Wp + (size_t)rw * 512 + pl * 256 + kc + sg * 8);
        }
#pragma unroll
        for (int i = tid; i < 2048; i += 512) {      // B: 256 rows x 8 segs
            int rw = (i >> 3) & 255, sg = i & 7;
            cpa16(st + 2u * (18432 + rw * 72 + sg * 8),
                  Sp + (size_t)rw * KP2 + kc + sg * 8);
        }
        asm volatile("cp.async.commit_group;" ::: "memory");
    };

    int lrow = lane & 15, lc8 = (lane >> 4) * 8;     // ldmatrix address split
    load_stage(0, 0);

    for (int c = 0; c < 4; c++) {
        if (c < 3) load_stage((c + 1) & 1, (c + 1) * 64);
        if (c < 3) asm volatile("cp.async.wait_group 1;" ::: "memory");
        else       asm volatile("cp.async.wait_group 0;" ::: "memory");
        __syncthreads();

        uint32_t st = sbase + (uint32_t)(c & 1) * STG_B;
        uint32_t aA = st + 2u * ((wm * 32 + lrow) * 72 + lc8);
        uint32_t aB = st + 2u * (18432 + (wn * 64 + lrow) * 72 + lc8);

#pragma unroll
        for (int ks = 0; ks < 4; ks++) {
            uint32_t ko = 2u * (ks * 16);
            uint32_t ah[2][4], al[2][4], b[4][4];
#pragma unroll
            for (int mt = 0; mt < 2; mt++) LDSM4(ah[mt], aA + 2u * (mt * 16 * 72) + ko);
#pragma unroll
            for (int mt = 0; mt < 2; mt++) LDSM4(al[mt], aA + 2u * (9216 + mt * 16 * 72) + ko);
#pragma unroll
            for (int p = 0; p < 4; p++)    LDSM4(b[p], aB + 2u * (p * 16 * 72) + ko);
            // term 0: Ah * B
#pragma unroll
            for (int mt = 0; mt < 2; mt++)
#pragma unroll
                for (int nt = 0; nt < 8; nt++)
                    MMAH(acc[mt][nt], ah[mt], b[nt >> 1][nt & 1], b[nt >> 1][2 + (nt & 1)]);
            // term 1: Al * B
#pragma unroll
            for (int mt = 0; mt < 2; mt++)
#pragma unroll
                for (int nt = 0; nt < 8; nt++)
                    MMAH(acc[mt][nt], al[mt], b[nt >> 1][nt & 1], b[nt >> 1][2 + (nt & 1)]);
        }
        __syncthreads();
    }

    // ---- epilogue: bias + scatter to [B, COUT, 256, 256] ----
    int qrow = lane >> 2, qcol = (lane & 3) * 2;
#pragma unroll
    for (int mt = 0; mt < 2; mt++) {
        int mrow = m0 + wm * 32 + mt * 16 + qrow;
        float bi0 = g_bias[r * COUT + mrow];
        float bi1 = g_bias[r * COUT + mrow + 8];
#pragma unroll
        for (int nt = 0; nt < 8; nt++) {
            int nidx = n0 + wn * 64 + nt * 8 + qcol;
            int b2i = nidx >> 10, hw = nidx & 1023;
            int prow = hw >> 5, pcol = hw & 31;
            size_t off0 = (((size_t)(b2i * COUT + mrow) * 256 + gh * 32 + prow) * 256 +
                           gw * 32 + pcol);
            size_t off1 = off0 + (size_t)8 * 65536;          // mrow+8
            float2 v0 = make_float2(acc[mt][nt][0] + bi0, acc[mt][nt][1] + bi0);
            float2 v1 = make_float2(acc[mt][nt][2] + bi1, acc[mt][nt][3] + bi1);
            *(float2*)&out[off0] = v0;
            *(float2*)&out[off1] = v1;
        }
    }
}

// ---------------- launch ------------------------------------------------------
extern "C" void kernel_launch(void* const* d_in, const int* in_sizes, int n_in,
                              void* d_out, int out_size) {
    const float* x     = (const float*)d_in[0];
    const float* dw_w  = (const float*)d_in[1];
    const float* bn1_g = (const float*)d_in[2];
    const float* bn1_b = (const float*)d_in[3];
    const float* bn1_m = (const float*)d_in[4];
    const float* bn1_v = (const float*)d_in[5];
    const float* pw_w  = (const float*)d_in[6];
    const float* bn2_g = (const float*)d_in[7];
    const float* bn2_b = (const float*)d_in[8];
    const float* bn2_m = (const float*)d_in[9];
    const float* bn2_v = (const float*)d_in[10];
    const float* res_w = (const float*)d_in[11];
    float* out = (float*)d_out;

    cudaFuncSetAttribute(k_gemm, cudaFuncAttributeMaxDynamicSharedMemorySize,
                         2 * STG_B);
    cudaFuncSetAttribute(k_dw, cudaFuncAttributeMaxDynamicSharedMemorySize,
                         128 * CSTR * 4);

    k_prep<<<(RR * COUT * 256) / 256, 256>>>(pw_w, res_w, bn2_g, bn2_b, bn2_m, bn2_v);
    k_dw<<<RR * BB * 8, 512, 128 * CSTR * 4>>>(x, dw_w, bn1_g, bn1_b, bn1_m, bn1_v);
    // x = m-block fastest: the 2 CTAs sharing one B tile run adjacently (L2 reuse)
    dim3 grid(COUT / 128, NN / 256, RR);
    k_gemm<<<grid, 512, 2 * STG_B>>>(out);
}

// round 9
// speedup vs baseline: 3.1729x; 1.3213x over previous
#include <cuda_runtime.h>
#include <cuda_bf16.h>
#include <cuda_fp16.h>
#include <cstdint>

#define GH 8
#define GW 8
#define RR 64
#define BB 8
#define CIN 128
#define COUT 256
#define NPIX 1024
#define NN 8192           // GEMM N per region (BB*NPIX)
#define KP2 256           // packed K: [gelu(128) | x(128)] fp16
#define EPSV 1e-5f

// ---------------- scratch (device globals; no runtime allocation) -------------
__device__ __half g_Sh[(size_t)RR * NN * KP2];            // 256 MB
__device__ __half g_Wh[(size_t)RR * COUT * KP2];          // 8 MB
__device__ float g_bias[RR * COUT];

// ---------------- helpers -----------------------------------------------------
__device__ __forceinline__ uint32_t smem_u32(const void* p) {
    uint32_t a;
    asm("{ .reg .u64 t; cvta.to.shared.u64 t, %1; cvt.u32.u64 %0, t; }" : "=r"(a) : "l"(p));
    return a;
}
__device__ __forceinline__ void cpa16(uint32_t dst, const void* src) {
    asm volatile("cp.async.cg.shared.global [%0], [%1], 16;" :: "r"(dst), "l"(src) : "memory");
}
#define LDSM4(d, addr)                                                          \
    asm volatile("ldmatrix.sync.aligned.m8n8.x4.shared.b16 {%0,%1,%2,%3}, [%4];" \
                 : "=r"((d)[0]), "=r"((d)[1]), "=r"((d)[2]), "=r"((d)[3])        \
                 : "r"(addr))
#define MMAH(c, a, b0v, b1v)                                                     \
    asm volatile("mma.sync.aligned.m16n8k16.row.col.f32.f16.f16.f32 "            \
                 "{%0,%1,%2,%3},{%4,%5,%6,%7},{%8,%9},{%0,%1,%2,%3};"            \
                 : "+f"((c)[0]), "+f"((c)[1]), "+f"((c)[2]), "+f"((c)[3])        \
                 : "r"((a)[0]), "r"((a)[1]), "r"((a)[2]), "r"((a)[3]),           \
                   "r"(b0v), "r"(b1v))

// ---------------- kernel 0: fold BN2 into fp16 weights ------------------------
__global__ __launch_bounds__(256) void k_prep(const float* __restrict__ pw_w,
                                              const float* __restrict__ res_w,
                                              const float* __restrict__ g2,
                                              const float* __restrict__ b2,
                                              const float* __restrict__ m2,
                                              const float* __restrict__ v2) {
    int idx = blockIdx.x * 256 + threadIdx.x;      // RR*COUT*256
    int r = idx >> 16;
    int rem = idx & 65535;
    int o = rem >> 8;
    int k = rem & 255;
    int ro = r * COUT + o;
    float rs = rsqrtf(v2[ro] + EPSV);
    float scv = g2[ro] * rs;
    float wv = (k < CIN) ? scv * pw_w[(size_t)ro * CIN + k]
                         : res_w[(size_t)ro * CIN + (k - CIN)];
    g_Wh[(size_t)ro * KP2 + k] = __float2half(wv);
    if (k == 0) g_bias[ro] = b2[ro] - g2[ro] * m2[ro] * rs;
}

// ---------------- kernel 1: dw 3x3 + BN1 + GELU -> S[r][n][k] fp16 ------------
#define CSTR 205   // 6*34 + 1 (odd -> conflict-free channel stride)
__global__ __launch_bounds__(512) void k_dw(const float* __restrict__ x,
                                            const float* __restrict__ dw_w,
                                            const float* __restrict__ g1,
                                            const float* __restrict__ b1,
                                            const float* __restrict__ m1,
                                            const float* __restrict__ v1) {
    extern __shared__ float sx[];  // [128 ch][6 rows][34 cols], stride CSTR
    int bxx = blockIdx.x;
    int chunk = bxx & 7, bb = (bxx >> 3) & 7, r = bxx >> 6;
    int gh = r >> 3, gw = r & 7;
    int tid = threadIdx.x;
    int r0 = chunk * 4;

    for (int i = tid; i < 128 * CSTR; i += 512) sx[i] = 0.f;
    __syncthreads();
    for (int i = tid; i < 6 * 128 * 32; i += 512) {
        int rr = i >> 12;
        int c = (i >> 5) & 127;
        int col = i & 31;
        int g = r0 - 1 + rr;
        if (g >= 0 && g < 32)
            sx[c * CSTR + rr * 34 + 1 + col] =
                x[(((size_t)(bb * CIN + c)) * 256 + gh * 32 + g) * 256 + gw * 32 + col];
    }
    __syncthreads();

    int c = tid & 127, ps = tid >> 7;
    int rc = r * CIN + c;
    float w9[9];
    const float* wp = dw_w + (size_t)rc * 9;
#pragma unroll
    for (int i = 0; i < 9; i++) w9[i] = wp[i];
    float rs = rsqrtf(v1[rc] + EPSV);
    float sc = g1[rc] * rs;
    float sh = b1[rc] - g1[rc] * m1[rc] * rs;

    int row = r0 + ps;
    const float* sb = sx + c * CSTR + ps * 34;
    __half* Sp = g_Sh + ((size_t)r * NN + (size_t)bb * NPIX + (size_t)row * 32) * KP2;

#pragma unroll 4
    for (int col = 0; col < 32; col++) {
        float acc = 0.f;
#pragma unroll
        for (int dr = 0; dr < 3; dr++)
#pragma unroll
            for (int dc = 0; dc < 3; dc++)
                acc = fmaf(sb[dr * 34 + col + dc], w9[dr * 3 + dc], acc);
        float yv = fmaf(acc, sc, sh);
        float gv = yv * normcdff(yv);               // exact GELU
        float xv = sb[34 + col + 1];
        __half* o = Sp + (size_t)col * KP2;
        o[c] = __float2half(gv);
        o[128 + c] = __float2half(xv);
    }
}

// ---------------- kernel 2: fp16 1-term warp-MMA GEMM + epilogue --------------
// CTA tile 128m x 256n, 512 threads / 16 warps (warp tile 32x64), K-chunk 64.
// SMEM per stage (halfs): A @0 (128x72), B @9216 (256x72).
#define STG_E 27648
#define STG_B (STG_E * 2)          // 55296 bytes/stage

__global__ __launch_bounds__(512, 1) void k_gemm(float* __restrict__ out) {
    extern __shared__ __half smb[];
    uint32_t sbase = smem_u32(smb);
    int tid = threadIdx.x, lane = tid & 31, wid = tid >> 5;
    int wm = wid & 3, wn = wid >> 2;                 // 4x4 warp grid; warp = 32m x 64n
    int m0 = blockIdx.x * 128, n0 = blockIdx.y * 256, r = blockIdx.z;
    int gh = r >> 3, gw = r & 7;

    const __half* Wp = g_Wh + (size_t)(r * COUT + m0) * KP2;
    const __half* Sp = g_Sh + ((size_t)r * NN + n0) * KP2;

    float acc[2][8][4];
#pragma unroll
    for (int i = 0; i < 2; i++)
#pragma unroll
        for (int j = 0; j < 8; j++)
#pragma unroll
            for (int t = 0; t < 4; t++) acc[i][j][t] = 0.f;

    // cp.async load of one stage: A (128x64) + B (256x64)
    auto load_stage = [&](int s, int kc) {
        uint32_t st = sbase + (uint32_t)s * STG_B;
#pragma unroll
        for (int i = tid; i < 1024; i += 512) {      // A: 128 rows x 8 segs
            int rw = i >> 3, sg = i & 7;
            cpa16(st + 2u * (rw * 72 + sg * 8),
                  Wp + (size_t)rw * KP2 + kc + sg * 8);
        }
#pragma unroll
        for (int i = tid; i < 2048; i += 512) {      // B: 256 rows x 8 segs
            int rw = (i >> 3) & 255, sg = i & 7;
            cpa16(st + 2u * (9216 + rw * 72 + sg * 8),
                  Sp + (size_t)rw * KP2 + kc + sg * 8);
        }
        asm volatile("cp.async.commit_group;" ::: "memory");
    };

    int lrow = lane & 15, lc8 = (lane >> 4) * 8;     // ldmatrix address split
    load_stage(0, 0);

    for (int c = 0; c < 4; c++) {
        if (c < 3) load_stage((c + 1) & 1, (c + 1) * 64);
        if (c < 3) asm volatile("cp.async.wait_group 1;" ::: "memory");
        else       asm volatile("cp.async.wait_group 0;" ::: "memory");
        __syncthreads();

        uint32_t st = sbase + (uint32_t)(c & 1) * STG_B;
        uint32_t aA = st + 2u * ((wm * 32 + lrow) * 72 + lc8);
        uint32_t aB = st + 2u * (9216 + (wn * 64 + lrow) * 72 + lc8);

#pragma unroll
        for (int ks = 0; ks < 4; ks++) {
            uint32_t ko = 2u * (ks * 16);
            uint32_t ah[2][4], b[4][4];
#pragma unroll
            for (int mt = 0; mt < 2; mt++) LDSM4(ah[mt], aA + 2u * (mt * 16 * 72) + ko);
#pragma unroll
            for (int p = 0; p < 4; p++)    LDSM4(b[p], aB + 2u * (p * 16 * 72) + ko);
#pragma unroll
            for (int mt = 0; mt < 2; mt++)
#pragma unroll
                for (int nt = 0; nt < 8; nt++)
                    MMAH(acc[mt][nt], ah[mt], b[nt >> 1][nt & 1], b[nt >> 1][2 + (nt & 1)]);
        }
        __syncthreads();
    }

    // ---- epilogue: bias + scatter to [B, COUT, 256, 256] ----
    int qrow = lane >> 2, qcol = (lane & 3) * 2;
#pragma unroll
    for (int mt = 0; mt < 2; mt++) {
        int mrow = m0 + wm * 32 + mt * 16 + qrow;
        float bi0 = g_bias[r * COUT + mrow];
        float bi1 = g_bias[r * COUT + mrow + 8];
#pragma unroll
        for (int nt = 0; nt < 8; nt++) {
            int nidx = n0 + wn * 64 + nt * 8 + qcol;
            int b2i = nidx >> 10, hw = nidx & 1023;
            int prow = hw >> 5, pcol = hw & 31;
            size_t off0 = (((size_t)(b2i * COUT + mrow) * 256 + gh * 32 + prow) * 256 +
                           gw * 32 + pcol);
            size_t off1 = off0 + (size_t)8 * 65536;          // mrow+8
            float2 v0 = make_float2(acc[mt][nt][0] + bi0, acc[mt][nt][1] + bi0);
            float2 v1 = make_float2(acc[mt][nt][2] + bi1, acc[mt][nt][3] + bi1);
            *(float2*)&out[off0] = v0;
            *(float2*)&out[off1] = v1;
        }
    }
}

// ---------------- launch ------------------------------------------------------
extern "C" void kernel_launch(void* const* d_in, const int* in_sizes, int n_in,
                              void* d_out, int out_size) {
    const float* x     = (const float*)d_in[0];
    const float* dw_w  = (const float*)d_in[1];
    const float* bn1_g = (const float*)d_in[2];
    const float* bn1_b = (const float*)d_in[3];
    const float* bn1_m = (const float*)d_in[4];
    const float* bn1_v = (const float*)d_in[5];
    const float* pw_w  = (const float*)d_in[6];
    const float* bn2_g = (const float*)d_in[7];
    const float* bn2_b = (const float*)d_in[8];
    const float* bn2_m = (const float*)d_in[9];
    const float* bn2_v = (const float*)d_in[10];
    const float* res_w = (const float*)d_in[11];
    float* out = (float*)d_out;

    cudaFuncSetAttribute(k_gemm, cudaFuncAttributeMaxDynamicSharedMemorySize,
                         2 * STG_B);
    cudaFuncSetAttribute(k_dw, cudaFuncAttributeMaxDynamicSharedMemorySize,
                         128 * CSTR * 4);

    k_prep<<<(RR * COUT * 256) / 256, 256>>>(pw_w, res_w, bn2_g, bn2_b, bn2_m, bn2_v);
    k_dw<<<RR * BB * 8, 512, 128 * CSTR * 4>>>(x, dw_w, bn1_g, bn1_b, bn1_m, bn1_v);
    // x = m-block fastest: the 2 CTAs sharing one B tile run adjacently (L2 reuse)
    dim3 grid(COUT / 128, NN / 256, RR);
    k_gemm<<<grid, 512, 2 * STG_B>>>(out);
}